// round 1
// baseline (speedup 1.0000x reference)
#include <cuda_runtime.h>
#include <cuda_bf16.h>

#define BATCH 1024
#define NF    256
#define NC    100000
#define EPSV  1e-12f
#define MOM   0.5f
#define SCLR  30.0f

// out layout: predicts [BATCH*NC] | targets [BATCH] | new_weight [NC*NF]
#define TGT_OFF  ((size_t)BATCH * (size_t)NC)
#define WOUT_OFF (TGT_OFF + (size_t)BATCH)

__device__ float g_nw[NC];
__device__ float g_nx[BATCH];

// ---------------------------------------------------------------------------
// Kernel 1: row norms of weight + copy weight into output new_weight region
// one warp per row (256 floats = 2x float4 per lane)
// ---------------------------------------------------------------------------
__global__ void norm_copy_w_kernel(const float* __restrict__ w, float* __restrict__ wout) {
    int warp = threadIdx.x >> 5;
    int lane = threadIdx.x & 31;
    int row  = blockIdx.x * 8 + warp;
    if (row >= NC) return;
    const float4* src = (const float4*)(w + (size_t)row * NF);
    float4*       dst = (float4*)(wout + (size_t)row * NF);
    float4 v0 = src[lane];
    float4 v1 = src[lane + 32];
    dst[lane]      = v0;
    dst[lane + 32] = v1;
    float ss = v0.x*v0.x + v0.y*v0.y + v0.z*v0.z + v0.w*v0.w
             + v1.x*v1.x + v1.y*v1.y + v1.z*v1.z + v1.w*v1.w;
    #pragma unroll
    for (int o = 16; o; o >>= 1) ss += __shfl_xor_sync(0xffffffffu, ss, o);
    if (lane == 0) g_nw[row] = sqrtf(ss);
}

// ---------------------------------------------------------------------------
// Kernel 2: row norms of inputs
// ---------------------------------------------------------------------------
__global__ void norm_x_kernel(const float* __restrict__ x) {
    int warp = threadIdx.x >> 5;
    int lane = threadIdx.x & 31;
    int row  = blockIdx.x * 8 + warp;
    if (row >= BATCH) return;
    const float4* src = (const float4*)(x + (size_t)row * NF);
    float4 v0 = src[lane];
    float4 v1 = src[lane + 32];
    float ss = v0.x*v0.x + v0.y*v0.y + v0.z*v0.z + v0.w*v0.w
             + v1.x*v1.x + v1.y*v1.y + v1.z*v1.z + v1.w*v1.w;
    #pragma unroll
    for (int o = 16; o; o >>= 1) ss += __shfl_xor_sync(0xffffffffu, ss, o);
    if (lane == 0) g_nx[row] = sqrtf(ss);
}

// ---------------------------------------------------------------------------
// Kernel 3: SGEMM  C[m,n] = dot(x[m,:], w[n,:]) * 30 / (|x_m| * |w_n|)
// 128x128 tile, BK=8, 256 threads, 8x8 per thread, double-buffered smem
// grid = (8 m-tiles [x, fast], 782 n-tiles [y]) for weight L2 reuse
// ---------------------------------------------------------------------------
__global__ void __launch_bounds__(256) gemm_kernel(const float* __restrict__ A,
                                                   const float* __restrict__ Bw,
                                                   float* __restrict__ C) {
    __shared__ float As[2][8][128];
    __shared__ float Bs[2][8][128];
    __shared__ float sinx[128];
    __shared__ float sinw[128];

    const int tid = threadIdx.x;
    const int m0 = blockIdx.x * 128;
    const int n0 = blockIdx.y * 128;

    if (tid < 128) {
        sinx[tid] = SCLR / fmaxf(g_nx[m0 + tid], EPSV);
        int n = n0 + tid;
        sinw[tid] = (n < NC) ? (1.0f / fmaxf(g_nw[n], EPSV)) : 0.0f;
    }

    const int lr = tid >> 1;         // 0..127 : row within tile for global loads
    const int lc = (tid & 1) * 4;    // 0 or 4 : k-offset for global loads
    const float* Aptr = A + (size_t)(m0 + lr) * NF + lc;
    const int brow = n0 + lr;
    const float* Bptr = Bw + (size_t)brow * NF + lc;
    const bool bvalid = (brow < NC);

    float acc[8][8];
    #pragma unroll
    for (int i = 0; i < 8; i++)
        #pragma unroll
        for (int j = 0; j < 8; j++) acc[i][j] = 0.0f;

    // prologue: tile 0
    float4 av = *(const float4*)Aptr;
    float4 bv = bvalid ? *(const float4*)Bptr : make_float4(0.f, 0.f, 0.f, 0.f);
    As[0][lc + 0][lr] = av.x; As[0][lc + 1][lr] = av.y;
    As[0][lc + 2][lr] = av.z; As[0][lc + 3][lr] = av.w;
    Bs[0][lc + 0][lr] = bv.x; Bs[0][lc + 1][lr] = bv.y;
    Bs[0][lc + 2][lr] = bv.z; Bs[0][lc + 3][lr] = bv.w;
    __syncthreads();

    const int ty = tid >> 4;   // 0..15
    const int tx = tid & 15;   // 0..15
    int cur = 0;

    for (int kt = 0; kt < 32; kt++) {
        if (kt < 31) {
            av = *(const float4*)(Aptr + (kt + 1) * 8);
            bv = bvalid ? *(const float4*)(Bptr + (kt + 1) * 8)
                        : make_float4(0.f, 0.f, 0.f, 0.f);
        }
        #pragma unroll
        for (int k = 0; k < 8; k++) {
            float4 a0 = *(const float4*)&As[cur][k][ty * 4];
            float4 a1 = *(const float4*)&As[cur][k][64 + ty * 4];
            float4 b0 = *(const float4*)&Bs[cur][k][tx * 4];
            float4 b1 = *(const float4*)&Bs[cur][k][64 + tx * 4];
            float ar[8] = {a0.x, a0.y, a0.z, a0.w, a1.x, a1.y, a1.z, a1.w};
            float br[8] = {b0.x, b0.y, b0.z, b0.w, b1.x, b1.y, b1.z, b1.w};
            #pragma unroll
            for (int i = 0; i < 8; i++)
                #pragma unroll
                for (int j = 0; j < 8; j++)
                    acc[i][j] = fmaf(ar[i], br[j], acc[i][j]);
        }
        if (kt < 31) {
            int nxt = cur ^ 1;
            As[nxt][lc + 0][lr] = av.x; As[nxt][lc + 1][lr] = av.y;
            As[nxt][lc + 2][lr] = av.z; As[nxt][lc + 3][lr] = av.w;
            Bs[nxt][lc + 0][lr] = bv.x; Bs[nxt][lc + 1][lr] = bv.y;
            Bs[nxt][lc + 2][lr] = bv.z; Bs[nxt][lc + 3][lr] = bv.w;
            __syncthreads();
            cur = nxt;
        }
    }

    // epilogue: scale by 30/(|x_m||w_n|) and store (guard last n-tile)
    #pragma unroll
    for (int i = 0; i < 8; i++) {
        int r = (i < 4) ? (ty * 4 + i) : (64 + ty * 4 + (i - 4));
        float sx = sinx[r];
        #pragma unroll
        for (int cg = 0; cg < 2; cg++) {
            int cb = cg * 64 + tx * 4;
            int gc = n0 + cb;
            float4 v;
            v.x = acc[i][cg * 4 + 0] * sx * sinw[cb + 0];
            v.y = acc[i][cg * 4 + 1] * sx * sinw[cb + 1];
            v.z = acc[i][cg * 4 + 2] * sx * sinw[cb + 2];
            v.w = acc[i][cg * 4 + 3] * sx * sinw[cb + 3];
            float* cp = C + (size_t)(m0 + r) * NC + gc;
            if (gc + 3 < NC) {
                *(float4*)cp = v;
            } else {
                if (gc + 0 < NC) cp[0] = v.x;
                if (gc + 1 < NC) cp[1] = v.y;
                if (gc + 2 < NC) cp[2] = v.z;
            }
        }
    }
}

// ---------------------------------------------------------------------------
// Kernel 4: targets as float
// ---------------------------------------------------------------------------
__global__ void tgt_kernel(const int* __restrict__ tg, float* __restrict__ out) {
    int i = blockIdx.x * 256 + threadIdx.x;
    if (i < BATCH) out[i] = (float)tg[i];
}

// ---------------------------------------------------------------------------
// Kernel 5: sequential momentum update, parallel over distinct classes.
// Block i owns class targets[i] iff i is the first occurrence; it then walks
// the occurrence chain sequentially. 64 threads per block, row in registers.
// Operates in-place on the new_weight region of d_out (already a raw copy).
// ---------------------------------------------------------------------------
__global__ void update_kernel(const float* __restrict__ x,
                              const int* __restrict__ tg,
                              float* __restrict__ wout) {
    __shared__ int st[BATCH];
    __shared__ float sred[2];
    const int t = threadIdx.x;  // 0..63
    for (int j = t; j < BATCH; j += 64) st[j] = tg[j];
    __syncthreads();

    const int i = blockIdx.x;
    const int y = st[i];
    for (int j = 0; j < i; j++)
        if (st[j] == y) return;  // not first occurrence (uniform across block)

    float4 r = *(float4*)(wout + (size_t)y * NF + t * 4);

    for (int j = i; j < BATCH; j++) {
        if (st[j] != y) continue;  // uniform condition
        float invn = 1.0f / fmaxf(g_nx[j], EPSV);
        float4 xv = *(const float4*)(x + (size_t)j * NF + t * 4);
        r.x = MOM * r.x + (1.0f - MOM) * xv.x * invn;
        r.y = MOM * r.y + (1.0f - MOM) * xv.y * invn;
        r.z = MOM * r.z + (1.0f - MOM) * xv.z * invn;
        r.w = MOM * r.w + (1.0f - MOM) * xv.w * invn;
        float ss = r.x*r.x + r.y*r.y + r.z*r.z + r.w*r.w;
        #pragma unroll
        for (int o = 16; o; o >>= 1) ss += __shfl_xor_sync(0xffffffffu, ss, o);
        if ((t & 31) == 0) sred[t >> 5] = ss;
        __syncthreads();
        float inv = 1.0f / fmaxf(sqrtf(sred[0] + sred[1]), EPSV);
        __syncthreads();
        r.x *= inv; r.y *= inv; r.z *= inv; r.w *= inv;
    }

    *(float4*)(wout + (size_t)y * NF + t * 4) = r;
}

// ---------------------------------------------------------------------------
extern "C" void kernel_launch(void* const* d_in, const int* in_sizes, int n_in,
                              void* d_out, int out_size) {
    const float* inputs  = (const float*)d_in[0];
    const int*   targets = (const int*)d_in[1];
    const float* weight  = (const float*)d_in[2];
    float* out = (float*)d_out;

    norm_copy_w_kernel<<<NC / 8, 256>>>(weight, out + WOUT_OFF);
    norm_x_kernel<<<BATCH / 8, 256>>>(inputs);
    gemm_kernel<<<dim3(8, (NC + 127) / 128), 256>>>(inputs, weight, out);
    tgt_kernel<<<4, 256>>>(targets, out + TGT_OFF);
    update_kernel<<<BATCH, 64>>>(inputs, targets, out + WOUT_OFF);
}

// round 4
// speedup vs baseline: 1.7470x; 1.7470x over previous
#include <cuda_runtime.h>
#include <cuda_bf16.h>
#include <cstdint>

#define BATCH 1024
#define NF    256
#define NC    100000
#define EPSV  1e-12f
#define MOM   0.5f
#define SCLR  30.0f

// out layout: predicts [BATCH*NC] | targets [BATCH] | new_weight [NC*NF]
#define TGT_OFF  ((size_t)BATCH * (size_t)NC)
#define WOUT_OFF (TGT_OFF + (size_t)BATCH)

__device__ float g_nw[NC];
__device__ float g_nx[BATCH];

__device__ __forceinline__ uint32_t f2tf(float f) {
    uint32_t r; asm("cvt.rna.tf32.f32 %0, %1;" : "=r"(r) : "f"(f)); return r;
}

__device__ __forceinline__ void mma_tf32(float* c, const uint32_t* a, uint32_t b0, uint32_t b1) {
    asm volatile(
        "mma.sync.aligned.m16n8k8.row.col.f32.tf32.tf32.f32 "
        "{%0,%1,%2,%3}, {%4,%5,%6,%7}, {%8,%9}, {%0,%1,%2,%3};"
        : "+f"(c[0]), "+f"(c[1]), "+f"(c[2]), "+f"(c[3])
        : "r"(a[0]), "r"(a[1]), "r"(a[2]), "r"(a[3]), "r"(b0), "r"(b1));
}

// ---------------------------------------------------------------------------
// SGEMM via mma.sync tf32: C[m,n] = dot(x[m],w[n]) * 30/(|x_m||w_n|)
// BM=128 BN=128 BK=16, 256 threads, warp grid 4m x 2n, warp tile 32x64
// SMEM k-major with pad 132 -> conflict-free fragment loads
// ---------------------------------------------------------------------------
#define BK   16
#define PAD  132

__global__ void __launch_bounds__(256, 2)
gemm_kernel(const float* __restrict__ A, const float* __restrict__ Bw,
            float* __restrict__ C) {
    __shared__ uint32_t As[2][BK][PAD];
    __shared__ uint32_t Bs[2][BK][PAD];
    __shared__ float sinx[128];
    __shared__ float sinw[128];

    const int tid  = threadIdx.x;
    const int m0   = blockIdx.x * 128;
    const int n0   = blockIdx.y * 128;
    const int lane = tid & 31;
    const int wid  = tid >> 5;
    const int wm   = wid >> 1;            // 0..3
    const int wn   = wid & 1;             // 0..1
    const int g    = lane >> 2;           // 0..7
    const int tg   = lane & 3;            // 0..3
    const int rb   = wm * 32;
    const int cb   = wn * 64;

    if (tid < 128) {
        sinx[tid] = SCLR / fmaxf(g_nx[m0 + tid], EPSV);
        int n = n0 + tid;
        sinw[tid] = (n < NC) ? (1.0f / fmaxf(g_nw[n], EPSV)) : 0.0f;
    }

    // global loader mapping: f in [0,512): row = f>>2 (0..127), kq = f&3
    const int r0 = tid >> 2;               // f = tid       -> row
    const int r1 = (tid + 256) >> 2;       // f = tid+256
    const int kq = tid & 3;
    const float* Ap0 = A + (size_t)(m0 + r0) * NF + kq * 4;
    const float* Ap1 = A + (size_t)(m0 + r1) * NF + kq * 4;
    const int gbr0 = n0 + r0, gbr1 = n0 + r1;
    const float* Bp0 = Bw + (size_t)gbr0 * NF + kq * 4;
    const float* Bp1 = Bw + (size_t)gbr1 * NF + kq * 4;
    const bool bv0 = gbr0 < NC, bv1 = gbr1 < NC;

    float acc[2][8][4];
    #pragma unroll
    for (int mf = 0; mf < 2; mf++)
        #pragma unroll
        for (int nf = 0; nf < 8; nf++)
            #pragma unroll
            for (int q = 0; q < 4; q++) acc[mf][nf][q] = 0.0f;

    // prologue: tile 0 into buffer 0
    float4 a0 = *(const float4*)Ap0;
    float4 a1 = *(const float4*)Ap1;
    float4 b0 = bv0 ? *(const float4*)Bp0 : make_float4(0.f,0.f,0.f,0.f);
    float4 b1 = bv1 ? *(const float4*)Bp1 : make_float4(0.f,0.f,0.f,0.f);
    {
        int kb = kq * 4;
        As[0][kb+0][r0] = f2tf(a0.x); As[0][kb+1][r0] = f2tf(a0.y);
        As[0][kb+2][r0] = f2tf(a0.z); As[0][kb+3][r0] = f2tf(a0.w);
        As[0][kb+0][r1] = f2tf(a1.x); As[0][kb+1][r1] = f2tf(a1.y);
        As[0][kb+2][r1] = f2tf(a1.z); As[0][kb+3][r1] = f2tf(a1.w);
        Bs[0][kb+0][r0] = f2tf(b0.x); Bs[0][kb+1][r0] = f2tf(b0.y);
        Bs[0][kb+2][r0] = f2tf(b0.z); Bs[0][kb+3][r0] = f2tf(b0.w);
        Bs[0][kb+0][r1] = f2tf(b1.x); Bs[0][kb+1][r1] = f2tf(b1.y);
        Bs[0][kb+2][r1] = f2tf(b1.z); Bs[0][kb+3][r1] = f2tf(b1.w);
    }
    __syncthreads();

    int cur = 0;
    #pragma unroll 1
    for (int kt = 0; kt < NF / BK; kt++) {
        if (kt + 1 < NF / BK) {
            int ko = (kt + 1) * BK;
            a0 = *(const float4*)(Ap0 + ko);
            a1 = *(const float4*)(Ap1 + ko);
            b0 = bv0 ? *(const float4*)(Bp0 + ko) : make_float4(0.f,0.f,0.f,0.f);
            b1 = bv1 ? *(const float4*)(Bp1 + ko) : make_float4(0.f,0.f,0.f,0.f);
        }
        #pragma unroll
        for (int s = 0; s < 2; s++) {
            uint32_t af[2][4];
            #pragma unroll
            for (int mf = 0; mf < 2; mf++) {
                int r = rb + mf * 16 + g;
                af[mf][0] = As[cur][8*s + tg    ][r    ];
                af[mf][1] = As[cur][8*s + tg    ][r + 8];
                af[mf][2] = As[cur][8*s + tg + 4][r    ];
                af[mf][3] = As[cur][8*s + tg + 4][r + 8];
            }
            #pragma unroll
            for (int nf = 0; nf < 8; nf++) {
                int n = cb + nf * 8 + g;
                uint32_t bf0 = Bs[cur][8*s + tg    ][n];
                uint32_t bf1 = Bs[cur][8*s + tg + 4][n];
                mma_tf32(acc[0][nf], af[0], bf0, bf1);
                mma_tf32(acc[1][nf], af[1], bf0, bf1);
            }
        }
        if (kt + 1 < NF / BK) {
            int nxt = cur ^ 1;
            int kb = kq * 4;
            __syncthreads();
            As[nxt][kb+0][r0] = f2tf(a0.x); As[nxt][kb+1][r0] = f2tf(a0.y);
            As[nxt][kb+2][r0] = f2tf(a0.z); As[nxt][kb+3][r0] = f2tf(a0.w);
            As[nxt][kb+0][r1] = f2tf(a1.x); As[nxt][kb+1][r1] = f2tf(a1.y);
            As[nxt][kb+2][r1] = f2tf(a1.z); As[nxt][kb+3][r1] = f2tf(a1.w);
            Bs[nxt][kb+0][r0] = f2tf(b0.x); Bs[nxt][kb+1][r0] = f2tf(b0.y);
            Bs[nxt][kb+2][r0] = f2tf(b0.z); Bs[nxt][kb+3][r0] = f2tf(b0.w);
            Bs[nxt][kb+0][r1] = f2tf(b1.x); Bs[nxt][kb+1][r1] = f2tf(b1.y);
            Bs[nxt][kb+2][r1] = f2tf(b1.z); Bs[nxt][kb+3][r1] = f2tf(b1.w);
            __syncthreads();
            cur = nxt;
        }
    }

    // epilogue: scale + direct float2 stores (32B-sector aligned)
    #pragma unroll
    for (int mf = 0; mf < 2; mf++) {
        int rr = rb + mf * 16 + g;
        float sxa = sinx[rr];
        float sxb = sinx[rr + 8];
        float* rowa = C + (size_t)(m0 + rr    ) * NC;
        float* rowb = C + (size_t)(m0 + rr + 8) * NC;
        #pragma unroll
        for (int nf = 0; nf < 8; nf++) {
            int cc = cb + nf * 8 + 2 * tg;
            int n  = n0 + cc;
            if (n < NC) {
                float sw0 = sinw[cc], sw1 = sinw[cc + 1];
                float2 va = make_float2(acc[mf][nf][0] * sxa * sw0,
                                        acc[mf][nf][1] * sxa * sw1);
                float2 vb = make_float2(acc[mf][nf][2] * sxb * sw0,
                                        acc[mf][nf][3] * sxb * sw1);
                *(float2*)(rowa + n) = va;
                *(float2*)(rowb + n) = vb;
            }
        }
    }
}

// ---------------------------------------------------------------------------
// Kernel: row norms of weight + copy weight into output new_weight region
// ---------------------------------------------------------------------------
__global__ void norm_copy_w_kernel(const float* __restrict__ w, float* __restrict__ wout) {
    int warp = threadIdx.x >> 5, lane = threadIdx.x & 31;
    int row = blockIdx.x * 8 + warp;
    if (row >= NC) return;
    const float4* src = (const float4*)(w + (size_t)row * NF);
    float4* dst = (float4*)(wout + (size_t)row * NF);
    float4 v0 = src[lane], v1 = src[lane + 32];
    dst[lane] = v0; dst[lane + 32] = v1;
    float ss = v0.x*v0.x + v0.y*v0.y + v0.z*v0.z + v0.w*v0.w
             + v1.x*v1.x + v1.y*v1.y + v1.z*v1.z + v1.w*v1.w;
    #pragma unroll
    for (int o = 16; o; o >>= 1) ss += __shfl_xor_sync(0xffffffffu, ss, o);
    if (lane == 0) g_nw[row] = sqrtf(ss);
}

__global__ void norm_x_kernel(const float* __restrict__ x) {
    int warp = threadIdx.x >> 5, lane = threadIdx.x & 31;
    int row = blockIdx.x * 8 + warp;
    if (row >= BATCH) return;
    const float4* src = (const float4*)(x + (size_t)row * NF);
    float4 v0 = src[lane], v1 = src[lane + 32];
    float ss = v0.x*v0.x + v0.y*v0.y + v0.z*v0.z + v0.w*v0.w
             + v1.x*v1.x + v1.y*v1.y + v1.z*v1.z + v1.w*v1.w;
    #pragma unroll
    for (int o = 16; o; o >>= 1) ss += __shfl_xor_sync(0xffffffffu, ss, o);
    if (lane == 0) g_nx[row] = sqrtf(ss);
}

__global__ void tgt_kernel(const int* __restrict__ tg, float* __restrict__ out) {
    int i = blockIdx.x * 256 + threadIdx.x;
    if (i < BATCH) out[i] = (float)tg[i];
}

// ---------------------------------------------------------------------------
// Sequential momentum update, parallel over distinct classes (chain walk)
// ---------------------------------------------------------------------------
__global__ void update_kernel(const float* __restrict__ x,
                              const int* __restrict__ tg,
                              float* __restrict__ wout) {
    __shared__ int st[BATCH];
    __shared__ float sred[2];
    const int t = threadIdx.x;
    for (int j = t; j < BATCH; j += 64) st[j] = tg[j];
    __syncthreads();
    const int i = blockIdx.x;
    const int y = st[i];
    for (int j = 0; j < i; j++)
        if (st[j] == y) return;
    float4 r = *(float4*)(wout + (size_t)y * NF + t * 4);
    for (int j = i; j < BATCH; j++) {
        if (st[j] != y) continue;
        float invn = 1.0f / fmaxf(g_nx[j], EPSV);
        float4 xv = *(const float4*)(x + (size_t)j * NF + t * 4);
        r.x = MOM * r.x + (1.0f - MOM) * xv.x * invn;
        r.y = MOM * r.y + (1.0f - MOM) * xv.y * invn;
        r.z = MOM * r.z + (1.0f - MOM) * xv.z * invn;
        r.w = MOM * r.w + (1.0f - MOM) * xv.w * invn;
        float ss = r.x*r.x + r.y*r.y + r.z*r.z + r.w*r.w;
        #pragma unroll
        for (int o = 16; o; o >>= 1) ss += __shfl_xor_sync(0xffffffffu, ss, o);
        if ((t & 31) == 0) sred[t >> 5] = ss;
        __syncthreads();
        float inv = 1.0f / fmaxf(sqrtf(sred[0] + sred[1]), EPSV);
        __syncthreads();
        r.x *= inv; r.y *= inv; r.z *= inv; r.w *= inv;
    }
    *(float4*)(wout + (size_t)y * NF + t * 4) = r;
}

// ---------------------------------------------------------------------------
extern "C" void kernel_launch(void* const* d_in, const int* in_sizes, int n_in,
                              void* d_out, int out_size) {
    const float* inputs  = (const float*)d_in[0];
    const int*   targets = (const int*)d_in[1];
    const float* weight  = (const float*)d_in[2];
    float* out = (float*)d_out;

    norm_copy_w_kernel<<<NC / 8, 256>>>(weight, out + WOUT_OFF);
    norm_x_kernel<<<BATCH / 8, 256>>>(inputs);
    gemm_kernel<<<dim3(8, (NC + 127) / 128), 256>>>(inputs, weight, out);
    tgt_kernel<<<4, 256>>>(targets, out + TGT_OFF);
    update_kernel<<<BATCH, 64>>>(inputs, targets, out + WOUT_OFF);
}

// round 5
// speedup vs baseline: 2.1528x; 1.2323x over previous
#include <cuda_runtime.h>
#include <cuda_bf16.h>
#include <cstdint>

#define BATCH 1024
#define NF    256
#define NC    100000
#define EPSV  1e-12f
#define MOM   0.5f
#define SCLR  30.0f

// out layout: predicts [BATCH*NC] | targets [BATCH] | new_weight [NC*NF]
#define TGT_OFF  ((size_t)BATCH * (size_t)NC)
#define WOUT_OFF (TGT_OFF + (size_t)BATCH)

__device__ float g_nw[NC];
__device__ float g_nx[BATCH];

__device__ __forceinline__ uint32_t f2tf(float f) {
    uint32_t r; asm("cvt.rna.tf32.f32 %0, %1;" : "=r"(r) : "f"(f)); return r;
}

__device__ __forceinline__ void mma_tf32(float* c, const uint32_t* a, uint32_t b0, uint32_t b1) {
    asm volatile(
        "mma.sync.aligned.m16n8k8.row.col.f32.tf32.tf32.f32 "
        "{%0,%1,%2,%3}, {%4,%5,%6,%7}, {%8,%9}, {%0,%1,%2,%3};"
        : "+f"(c[0]), "+f"(c[1]), "+f"(c[2]), "+f"(c[3])
        : "r"(a[0]), "r"(a[1]), "r"(a[2]), "r"(a[3]), "r"(b0), "r"(b1));
}

// ---------------------------------------------------------------------------
// SGEMM via mma.sync tf32: C[m,n] = dot(x[m],w[n]) * 30/(|x_m||w_n|)
// BM=128 BN=128 BK=16, 256 threads, warps 4m x 2n, warp tile 32x64.
// SMEM m-major [row][16] with XOR swizzle k' = k ^ (((row>>1)&3)<<2):
//   - fragment LDS conflict-free (banks {tg, g1, s^g2, g0} all distinct)
//   - loader does STS.128, granules distinct mod 8 per phase -> conflict-free
// One __syncthreads per stage (store to other buffer overlaps compute).
// ---------------------------------------------------------------------------
#define BK 16

__global__ void __launch_bounds__(256, 2)
gemm_kernel(const float* __restrict__ A, const float* __restrict__ Bw,
            float* __restrict__ C) {
    __shared__ uint32_t As[2][128][BK];
    __shared__ uint32_t Bs[2][128][BK];
    __shared__ float sinx[128];
    __shared__ float sinw[128];

    const int tid  = threadIdx.x;
    const int m0   = blockIdx.x * 128;
    const int n0   = blockIdx.y * 128;
    const int lane = tid & 31;
    const int wid  = tid >> 5;
    const int wm   = wid >> 1;            // 0..3
    const int wn   = wid & 1;             // 0..1
    const int g    = lane >> 2;           // 0..7
    const int tg   = lane & 3;            // 0..3
    const int rb   = wm * 32;
    const int cb   = wn * 64;

    if (tid < 128) {
        sinx[tid] = SCLR / fmaxf(g_nx[m0 + tid], EPSV);
        int n = n0 + tid;
        sinw[tid] = (n < NC) ? (1.0f / fmaxf(g_nw[n], EPSV)) : 0.0f;
    }

    // loader mapping: f in [0,512): row = f>>2, kq = f&3; f = tid, tid+256
    const int r0 = tid >> 2;
    const int r1 = r0 + 64;
    const int kq = tid & 3;
    const float* Ap0 = A + (size_t)(m0 + r0) * NF + kq * 4;
    const float* Ap1 = A + (size_t)(m0 + r1) * NF + kq * 4;
    const int gbr0 = n0 + r0, gbr1 = n0 + r1;
    const float* Bp0 = Bw + (size_t)gbr0 * NF + kq * 4;
    const float* Bp1 = Bw + (size_t)gbr1 * NF + kq * 4;
    const bool bv0 = gbr0 < NC, bv1 = gbr1 < NC;
    // swizzled store columns (float index of first of 4)
    const int sc0 = ((kq ^ ((r0 >> 1) & 3)) << 2);
    const int sc1 = ((kq ^ ((r1 >> 1) & 3)) << 2);

    float acc[2][8][4];
    #pragma unroll
    for (int mf = 0; mf < 2; mf++)
        #pragma unroll
        for (int nf = 0; nf < 8; nf++)
            #pragma unroll
            for (int q = 0; q < 4; q++) acc[mf][nf][q] = 0.0f;

    // prologue
    {
        float4 a0 = *(const float4*)Ap0;
        float4 a1 = *(const float4*)Ap1;
        float4 b0 = bv0 ? *(const float4*)Bp0 : make_float4(0.f,0.f,0.f,0.f);
        float4 b1 = bv1 ? *(const float4*)Bp1 : make_float4(0.f,0.f,0.f,0.f);
        *(uint4*)&As[0][r0][sc0] = make_uint4(f2tf(a0.x), f2tf(a0.y), f2tf(a0.z), f2tf(a0.w));
        *(uint4*)&As[0][r1][sc1] = make_uint4(f2tf(a1.x), f2tf(a1.y), f2tf(a1.z), f2tf(a1.w));
        *(uint4*)&Bs[0][r0][sc0] = make_uint4(f2tf(b0.x), f2tf(b0.y), f2tf(b0.z), f2tf(b0.w));
        *(uint4*)&Bs[0][r1][sc1] = make_uint4(f2tf(b1.x), f2tf(b1.y), f2tf(b1.z), f2tf(b1.w));
    }
    __syncthreads();

    const int swz = ((g >> 1) & 3) << 2;   // XOR for fragment k-index
    int cur = 0;

    #pragma unroll 1
    for (int kt = 0; kt < NF / BK; kt++) {
        float4 a0n, a1n, b0n, b1n;
        const bool more = (kt + 1 < NF / BK);
        if (more) {
            int ko = (kt + 1) * BK;
            a0n = *(const float4*)(Ap0 + ko);
            a1n = *(const float4*)(Ap1 + ko);
            b0n = bv0 ? *(const float4*)(Bp0 + ko) : make_float4(0.f,0.f,0.f,0.f);
            b1n = bv1 ? *(const float4*)(Bp1 + ko) : make_float4(0.f,0.f,0.f,0.f);
        }
        #pragma unroll
        for (int s = 0; s < 2; s++) {
            const int k0 = (8 * s + tg)     ^ swz;
            const int k1 = (8 * s + tg + 4) ^ swz;
            uint32_t af[2][4];
            #pragma unroll
            for (int mf = 0; mf < 2; mf++) {
                int r = rb + mf * 16 + g;
                af[mf][0] = As[cur][r    ][k0];
                af[mf][1] = As[cur][r + 8][k0];
                af[mf][2] = As[cur][r    ][k1];
                af[mf][3] = As[cur][r + 8][k1];
            }
            #pragma unroll
            for (int nf = 0; nf < 8; nf++) {
                int n = cb + nf * 8 + g;
                uint32_t bf0 = Bs[cur][n][k0];
                uint32_t bf1 = Bs[cur][n][k1];
                mma_tf32(acc[0][nf], af[0], bf0, bf1);
                mma_tf32(acc[1][nf], af[1], bf0, bf1);
            }
        }
        if (more) {
            int nxt = cur ^ 1;
            *(uint4*)&As[nxt][r0][sc0] = make_uint4(f2tf(a0n.x), f2tf(a0n.y), f2tf(a0n.z), f2tf(a0n.w));
            *(uint4*)&As[nxt][r1][sc1] = make_uint4(f2tf(a1n.x), f2tf(a1n.y), f2tf(a1n.z), f2tf(a1n.w));
            *(uint4*)&Bs[nxt][r0][sc0] = make_uint4(f2tf(b0n.x), f2tf(b0n.y), f2tf(b0n.z), f2tf(b0n.w));
            *(uint4*)&Bs[nxt][r1][sc1] = make_uint4(f2tf(b1n.x), f2tf(b1n.y), f2tf(b1n.z), f2tf(b1n.w));
            __syncthreads();
            cur = nxt;
        }
    }

    // epilogue: scale + direct float2 stores
    #pragma unroll
    for (int mf = 0; mf < 2; mf++) {
        int rr = rb + mf * 16 + g;
        float sxa = sinx[rr];
        float sxb = sinx[rr + 8];
        float* rowa = C + (size_t)(m0 + rr    ) * NC;
        float* rowb = C + (size_t)(m0 + rr + 8) * NC;
        #pragma unroll
        for (int nf = 0; nf < 8; nf++) {
            int cc = cb + nf * 8 + 2 * tg;
            int n  = n0 + cc;
            if (n < NC) {
                float sw0 = sinw[cc], sw1 = sinw[cc + 1];
                float2 va = make_float2(acc[mf][nf][0] * sxa * sw0,
                                        acc[mf][nf][1] * sxa * sw1);
                float2 vb = make_float2(acc[mf][nf][2] * sxb * sw0,
                                        acc[mf][nf][3] * sxb * sw1);
                *(float2*)(rowa + n) = va;
                *(float2*)(rowb + n) = vb;
            }
        }
    }
}

// ---------------------------------------------------------------------------
__global__ void norm_copy_w_kernel(const float* __restrict__ w, float* __restrict__ wout) {
    int warp = threadIdx.x >> 5, lane = threadIdx.x & 31;
    int row = blockIdx.x * 8 + warp;
    if (row >= NC) return;
    const float4* src = (const float4*)(w + (size_t)row * NF);
    float4* dst = (float4*)(wout + (size_t)row * NF);
    float4 v0 = src[lane], v1 = src[lane + 32];
    dst[lane] = v0; dst[lane + 32] = v1;
    float ss = v0.x*v0.x + v0.y*v0.y + v0.z*v0.z + v0.w*v0.w
             + v1.x*v1.x + v1.y*v1.y + v1.z*v1.z + v1.w*v1.w;
    #pragma unroll
    for (int o = 16; o; o >>= 1) ss += __shfl_xor_sync(0xffffffffu, ss, o);
    if (lane == 0) g_nw[row] = sqrtf(ss);
}

__global__ void norm_x_kernel(const float* __restrict__ x) {
    int warp = threadIdx.x >> 5, lane = threadIdx.x & 31;
    int row = blockIdx.x * 8 + warp;
    if (row >= BATCH) return;
    const float4* src = (const float4*)(x + (size_t)row * NF);
    float4 v0 = src[lane], v1 = src[lane + 32];
    float ss = v0.x*v0.x + v0.y*v0.y + v0.z*v0.z + v0.w*v0.w
             + v1.x*v1.x + v1.y*v1.y + v1.z*v1.z + v1.w*v1.w;
    #pragma unroll
    for (int o = 16; o; o >>= 1) ss += __shfl_xor_sync(0xffffffffu, ss, o);
    if (lane == 0) g_nx[row] = sqrtf(ss);
}

__global__ void tgt_kernel(const int* __restrict__ tg, float* __restrict__ out) {
    int i = blockIdx.x * 256 + threadIdx.x;
    if (i < BATCH) out[i] = (float)tg[i];
}

// ---------------------------------------------------------------------------
// Sequential momentum update, parallel over distinct classes (chain walk)
// ---------------------------------------------------------------------------
__global__ void update_kernel(const float* __restrict__ x,
                              const int* __restrict__ tg,
                              float* __restrict__ wout) {
    __shared__ int st[BATCH];
    __shared__ float sred[2];
    const int t = threadIdx.x;
    for (int j = t; j < BATCH; j += 64) st[j] = tg[j];
    __syncthreads();
    const int i = blockIdx.x;
    const int y = st[i];
    for (int j = 0; j < i; j++)
        if (st[j] == y) return;
    float4 r = *(float4*)(wout + (size_t)y * NF + t * 4);
    for (int j = i; j < BATCH; j++) {
        if (st[j] != y) continue;
        float invn = 1.0f / fmaxf(g_nx[j], EPSV);
        float4 xv = *(const float4*)(x + (size_t)j * NF + t * 4);
        r.x = MOM * r.x + (1.0f - MOM) * xv.x * invn;
        r.y = MOM * r.y + (1.0f - MOM) * xv.y * invn;
        r.z = MOM * r.z + (1.0f - MOM) * xv.z * invn;
        r.w = MOM * r.w + (1.0f - MOM) * xv.w * invn;
        float ss = r.x*r.x + r.y*r.y + r.z*r.z + r.w*r.w;
        #pragma unroll
        for (int o = 16; o; o >>= 1) ss += __shfl_xor_sync(0xffffffffu, ss, o);
        if ((t & 31) == 0) sred[t >> 5] = ss;
        __syncthreads();
        float inv = 1.0f / fmaxf(sqrtf(sred[0] + sred[1]), EPSV);
        __syncthreads();
        r.x *= inv; r.y *= inv; r.z *= inv; r.w *= inv;
    }
    *(float4*)(wout + (size_t)y * NF + t * 4) = r;
}

// ---------------------------------------------------------------------------
extern "C" void kernel_launch(void* const* d_in, const int* in_sizes, int n_in,
                              void* d_out, int out_size) {
    const float* inputs  = (const float*)d_in[0];
    const int*   targets = (const int*)d_in[1];
    const float* weight  = (const float*)d_in[2];
    float* out = (float*)d_out;

    norm_copy_w_kernel<<<NC / 8, 256>>>(weight, out + WOUT_OFF);
    norm_x_kernel<<<BATCH / 8, 256>>>(inputs);
    gemm_kernel<<<dim3(8, (NC + 127) / 128), 256>>>(inputs, weight, out);
    tgt_kernel<<<4, 256>>>(targets, out + TGT_OFF);
    update_kernel<<<BATCH, 64>>>(inputs, targets, out + WOUT_OFF);
}